// round 1
// baseline (speedup 1.0000x reference)
#include <cuda_runtime.h>
#include <math.h>

#define N 1024
#define DN 256
#define DE 128
#define DB 64
#define DH 48
#define NH 8
#define DQ 384   // NH*DH

// ---------------- scratch (global device arrays; no runtime alloc) ----------
__device__ float d_GW[DE * NH];        // g_edge[c] * Wb[c][h]
__device__ float d_WF[DB * NH];        // (W_bias @ Wb)[d][h]
__device__ float d_SGW[NH];            // sum_c GW[c][h]
__device__ float d_BW[NH];             // b_edge . Wb[:,h]
__device__ float d_q[N * DQ];          // rope'd, pre-scaled by 1/16
__device__ float d_kT[DQ * N];         // [h*48+d][j]
__device__ float d_v[N * DQ];          // row major [j][h*48+d]
__device__ float d_gate[N * DQ];
__device__ float d_bt[(size_t)N * NH * N];  // [i][h][j]  (32 MB)
__device__ float d_ao[N * DQ];         // gated attention output

// ---------------- K0: tiny precompute -------------------------------------
__global__ void k0_precompute(const float* __restrict__ g_edge,
                              const float* __restrict__ b_edge,
                              const float* __restrict__ W_bias,
                              const float* __restrict__ Wb) {
    int t = threadIdx.x;
    for (int idx = t; idx < DE * NH; idx += 256) {
        int c = idx >> 3;
        d_GW[idx] = g_edge[c] * Wb[idx];
    }
    for (int idx = t; idx < DB * NH; idx += 256) {
        int dd = idx >> 3, h = idx & 7;
        float s = 0.f;
        for (int c = 0; c < DE; c++) s += W_bias[dd * DE + c] * Wb[c * NH + h];
        d_WF[idx] = s;
    }
    if (t < NH) {
        float s = 0.f, b = 0.f;
        for (int c = 0; c < DE; c++) {
            s += g_edge[c] * Wb[c * NH + t];
            b += b_edge[c] * Wb[c * NH + t];
        }
        d_SGW[t] = s;
        d_BW[t] = b;
    }
}

// ---------------- K1: node LN + QKVG + rope + gate -------------------------
__global__ void __launch_bounds__(256) k1_node(
        const float* __restrict__ node, const float* __restrict__ node_pos,
        const float* __restrict__ g_node, const float* __restrict__ b_node,
        const float* __restrict__ Wq, const float* __restrict__ Wk,
        const float* __restrict__ Wv, const float* __restrict__ Wg,
        const float* __restrict__ bg) {
    __shared__ float x[8][DN];
    __shared__ float qt[8][DQ];
    __shared__ float kt[8][DQ];
    int t = threadIdx.x;
    int i0 = blockIdx.x * 8;
    int w = t >> 5, lane = t & 31;

    for (int r = 0; r < 8; r++) x[r][t] = node[(i0 + r) * DN + t];
    __syncthreads();

    // LN: warp w handles row w
    {
        float s = 0.f, sq = 0.f;
        for (int k = 0; k < 8; k++) {
            float v = x[w][lane + 32 * k];
            s += v; sq += v * v;
        }
        for (int o = 16; o > 0; o >>= 1) {
            s  += __shfl_xor_sync(0xffffffffu, s, o);
            sq += __shfl_xor_sync(0xffffffffu, sq, o);
        }
        float m = s * (1.f / DN);
        float var = sq * (1.f / DN) - m * m;
        float rs = rsqrtf(var + 1e-5f);
        for (int k = 0; k < 8; k++) {
            int c = lane + 32 * k;
            x[w][c] = (x[w][c] - m) * rs * g_node[c] + b_node[c];
        }
    }
    __syncthreads();

    // q, k raw
    for (int o = t; o < DQ; o += 256) {
        float acc[8];
        #pragma unroll
        for (int r = 0; r < 8; r++) acc[r] = 0.f;
        for (int c = 0; c < DN; c++) {
            float wv = Wq[c * DQ + o];
            #pragma unroll
            for (int r = 0; r < 8; r++) acc[r] = fmaf(x[r][c], wv, acc[r]);
        }
        #pragma unroll
        for (int r = 0; r < 8; r++) qt[r][o] = acc[r];

        #pragma unroll
        for (int r = 0; r < 8; r++) acc[r] = 0.f;
        for (int c = 0; c < DN; c++) {
            float wv = Wk[c * DQ + o];
            #pragma unroll
            for (int r = 0; r < 8; r++) acc[r] = fmaf(x[r][c], wv, acc[r]);
        }
        #pragma unroll
        for (int r = 0; r < 8; r++) kt[r][o] = acc[r];
    }
    __syncthreads();

    // rope + store q (scaled), kT
    for (int idx = t; idx < 8 * DQ; idx += 256) {
        int r = idx / DQ, o = idx % DQ;
        int h = o / DH, d = o % DH;
        int dd = (d < 24) ? d : d - 24;
        float pos = node_pos[i0 + r];
        float invf = expf(-0.38376418216567434f * (float)dd);  // ln(1e4)/24
        float th = pos * invf;
        float cs = cosf(th), sn = sinf(th);
        float q1 = qt[r][h * DH + dd], q2 = qt[r][h * DH + dd + 24];
        float k1 = kt[r][h * DH + dd], k2 = kt[r][h * DH + dd + 24];
        float qv = (d < 24) ? (q1 * cs - q2 * sn) : (q1 * sn + q2 * cs);
        float kv = (d < 24) ? (k1 * cs - k2 * sn) : (k1 * sn + k2 * cs);
        d_q[(i0 + r) * DQ + o] = qv * 0.0625f;  // 1/sqrt(256)
        d_kT[o * N + (i0 + r)] = kv;
    }

    // v, gate
    for (int o = t; o < DQ; o += 256) {
        float acc[8];
        #pragma unroll
        for (int r = 0; r < 8; r++) acc[r] = 0.f;
        for (int c = 0; c < DN; c++) {
            float wv = Wv[c * DQ + o];
            #pragma unroll
            for (int r = 0; r < 8; r++) acc[r] = fmaf(x[r][c], wv, acc[r]);
        }
        #pragma unroll
        for (int r = 0; r < 8; r++) d_v[(i0 + r) * DQ + o] = acc[r];

        #pragma unroll
        for (int r = 0; r < 8; r++) acc[r] = 0.f;
        for (int c = 0; c < DN; c++) {
            float wv = Wg[c * DQ + o];
            #pragma unroll
            for (int r = 0; r < 8; r++) acc[r] = fmaf(x[r][c], wv, acc[r]);
        }
        #pragma unroll
        for (int r = 0; r < 8; r++) {
            float z = acc[r] + bg[o];
            d_gate[(i0 + r) * DQ + o] = 1.f / (1.f + expf(-z));
        }
    }
}

// ---------------- K2: b_term from edge+bias (dominant, HBM-bound) ----------
// warp per (i,j) pair; block = 8 warps x 4 iterations = 32 pairs of row i
__global__ void __launch_bounds__(256) k2_bterm(const float* __restrict__ edge,
                                                const float* __restrict__ bias) {
    __shared__ float sb[NH][32];
    int t = threadIdx.x;
    int w = t >> 5, lane = t & 31;
    int i = blockIdx.y;
    int j0 = blockIdx.x * 32;

    // register-resident coefficients (lane-dependent)
    float GWr[4][8], WFr[2][8], SGWr[8], BWr[8];
    #pragma unroll
    for (int cc = 0; cc < 4; cc++) {
        const float* p = &d_GW[(lane * 4 + cc) * 8];
        float4 a = *(const float4*)p;
        float4 b = *(const float4*)(p + 4);
        GWr[cc][0] = a.x; GWr[cc][1] = a.y; GWr[cc][2] = a.z; GWr[cc][3] = a.w;
        GWr[cc][4] = b.x; GWr[cc][5] = b.y; GWr[cc][6] = b.z; GWr[cc][7] = b.w;
    }
    #pragma unroll
    for (int cc = 0; cc < 2; cc++) {
        const float* p = &d_WF[(lane * 2 + cc) * 8];
        float4 a = *(const float4*)p;
        float4 b = *(const float4*)(p + 4);
        WFr[cc][0] = a.x; WFr[cc][1] = a.y; WFr[cc][2] = a.z; WFr[cc][3] = a.w;
        WFr[cc][4] = b.x; WFr[cc][5] = b.y; WFr[cc][6] = b.z; WFr[cc][7] = b.w;
    }
    {
        float4 a = *(const float4*)&d_SGW[0];
        float4 b = *(const float4*)&d_SGW[4];
        SGWr[0] = a.x; SGWr[1] = a.y; SGWr[2] = a.z; SGWr[3] = a.w;
        SGWr[4] = b.x; SGWr[5] = b.y; SGWr[6] = b.z; SGWr[7] = b.w;
        float4 c = *(const float4*)&d_BW[0];
        float4 d = *(const float4*)&d_BW[4];
        BWr[0] = c.x; BWr[1] = c.y; BWr[2] = c.z; BWr[3] = c.w;
        BWr[4] = d.x; BWr[5] = d.y; BWr[6] = d.z; BWr[7] = d.w;
    }

    int j = j0 + w;  // it=0
    float4 e  = *(const float4*)&edge[(size_t)(i * N + j) * DE + lane * 4];
    float2 bv = *(const float2*)&bias[(size_t)(i * N + j) * DB + lane * 2];

    for (int it = 0; it < 4; it++) {
        float4 en; float2 bn;
        if (it < 3) {
            int jn = j0 + (it + 1) * 8 + w;
            en = *(const float4*)&edge[(size_t)(i * N + jn) * DE + lane * 4];
            bn = *(const float2*)&bias[(size_t)(i * N + jn) * DB + lane * 2];
        }
        float s  = e.x + e.y + e.z + e.w;
        float sq = e.x * e.x + e.y * e.y + e.z * e.z + e.w * e.w;
        #pragma unroll
        for (int o = 16; o > 0; o >>= 1) {
            s  += __shfl_xor_sync(0xffffffffu, s, o);
            sq += __shfl_xor_sync(0xffffffffu, sq, o);
        }
        float m = s * (1.f / DE);
        float var = sq * (1.f / DE) - m * m;
        float rs = rsqrtf(var + 1e-5f);

        float comb[8];
        #pragma unroll
        for (int h = 0; h < 8; h++) {
            float te = e.x * GWr[0][h] + e.y * GWr[1][h] + e.z * GWr[2][h] + e.w * GWr[3][h];
            float tb = bv.x * WFr[0][h] + bv.y * WFr[1][h];
            comb[h] = fmaf(rs, te, tb);
        }
        #pragma unroll
        for (int h = 0; h < 8; h++) {
            #pragma unroll
            for (int o = 16; o > 0; o >>= 1)
                comb[h] += __shfl_xor_sync(0xffffffffu, comb[h], o);
        }
        if (lane == 0) {
            int jj = it * 8 + w;
            float rm = rs * m;
            #pragma unroll
            for (int h = 0; h < 8; h++)
                sb[h][jj] = comb[h] - rm * SGWr[h] + BWr[h];
        }
        e = en; bv = bn;
        // note: j for next iter
    }
    __syncthreads();
    // coalesced write: [i][h][j]
    int h = t >> 5;
    int jj = t & 31;
    d_bt[((size_t)i * NH + h) * N + j0 + jj] = sb[h][jj];
}

// ---------------- K3: attention (per head, 16-row i tile) -------------------
#define TI 16
#define SPITCH 1025
__global__ void __launch_bounds__(256) k3_attn(const float* __restrict__ mask) {
    extern __shared__ float ss[];            // [TI][SPITCH]
    __shared__ float qs[TI * DH];
    __shared__ float inv[TI];
    __shared__ float maskr[TI];
    int t = threadIdx.x;
    int h = blockIdx.x;
    int i0 = blockIdx.y * TI;
    int w = t >> 5, lane = t & 31;

    for (int idx = t; idx < TI * DH; idx += 256) {
        int r = idx / DH, d = idx % DH;
        qs[idx] = d_q[(i0 + r) * DQ + h * DH + d];
    }
    if (t < TI) maskr[t] = mask[i0 + t];
    __syncthreads();

    // scores
    for (int jj = 0; jj < 4; jj++) {
        int j = t + jj * 256;
        float acc[TI];
        #pragma unroll
        for (int r = 0; r < TI; r++) acc[r] = 0.f;
        #pragma unroll 4
        for (int d = 0; d < DH; d++) {
            float kv = d_kT[(h * DH + d) * N + j];
            #pragma unroll
            for (int r = 0; r < TI; r++) acc[r] = fmaf(qs[r * DH + d], kv, acc[r]);
        }
        float mj = mask[j];
        #pragma unroll
        for (int r = 0; r < TI; r++) {
            float sm = 1000000.0f * (maskr[r] * mj - 1.f);
            float bt = d_bt[((size_t)(i0 + r) * NH + h) * N + j];
            ss[r * SPITCH + j] = acc[r] + bt + sm;
        }
    }
    __syncthreads();

    // softmax over j (warp per row, 2 rows per warp); keep unnormalized e, save 1/sum
    for (int rr = 0; rr < 2; rr++) {
        int r = w * 2 + rr;
        float mx = -1e30f;
        for (int k = 0; k < 32; k++)
            mx = fmaxf(mx, ss[r * SPITCH + lane + 32 * k]);
        #pragma unroll
        for (int o = 16; o > 0; o >>= 1)
            mx = fmaxf(mx, __shfl_xor_sync(0xffffffffu, mx, o));
        float sum = 0.f;
        for (int k = 0; k < 32; k++) {
            int c = r * SPITCH + lane + 32 * k;
            float ev = expf(ss[c] - mx);
            ss[c] = ev;
            sum += ev;
        }
        #pragma unroll
        for (int o = 16; o > 0; o >>= 1)
            sum += __shfl_xor_sync(0xffffffffu, sum, o);
        if (lane == 0) inv[r] = 1.f / sum;
    }
    __syncthreads();

    // PV: thread -> (r, d-quad). 16*12 = 192 active threads, float4 v loads
    if (t < TI * 12) {
        int r = t / 12, dq = t % 12;
        const float* vb = d_v + h * DH + dq * 4;
        float4 acc = make_float4(0.f, 0.f, 0.f, 0.f);
        const float* pr = &ss[r * SPITCH];
        #pragma unroll 4
        for (int j = 0; j < N; j++) {
            float p = pr[j];
            float4 v4 = *(const float4*)(vb + (size_t)j * DQ);
            acc.x = fmaf(p, v4.x, acc.x);
            acc.y = fmaf(p, v4.y, acc.y);
            acc.z = fmaf(p, v4.z, acc.z);
            acc.w = fmaf(p, v4.w, acc.w);
        }
        float iv = inv[r];
        int gi = (i0 + r) * DQ + h * DH + dq * 4;
        float4 g4 = *(const float4*)&d_gate[gi];
        float4 o4;
        o4.x = acc.x * iv * g4.x;
        o4.y = acc.y * iv * g4.y;
        o4.z = acc.z * iv * g4.z;
        o4.w = acc.w * iv * g4.w;
        *(float4*)&d_ao[gi] = o4;
    }
}

// ---------------- K4: Wo + LN + FFN + residual ------------------------------
__global__ void __launch_bounds__(256) k4_ffn(
        const float* __restrict__ node,
        const float* __restrict__ Wo, const float* __restrict__ g_ff,
        const float* __restrict__ b_ff, const float* __restrict__ W1,
        const float* __restrict__ b1, const float* __restrict__ W2,
        const float* __restrict__ b2, float* __restrict__ out) {
    __shared__ float ao[8][DQ];
    __shared__ float hn[8][DN];
    __shared__ float h1[8][2 * DN];
    int t = threadIdx.x;
    int i0 = blockIdx.x * 8;
    int w = t >> 5, lane = t & 31;

    for (int idx = t; idx < 8 * DQ; idx += 256) {
        int r = idx / DQ, c = idx % DQ;
        ao[r][c] = d_ao[(i0 + r) * DQ + c];
    }
    __syncthreads();

    // out-projection (Wo: 384x256)
    {
        float acc[8];
        #pragma unroll
        for (int r = 0; r < 8; r++) acc[r] = 0.f;
        for (int c = 0; c < DQ; c++) {
            float wv = Wo[c * DN + t];
            #pragma unroll
            for (int r = 0; r < 8; r++) acc[r] = fmaf(ao[r][c], wv, acc[r]);
        }
        #pragma unroll
        for (int r = 0; r < 8; r++) hn[r][t] = acc[r];
    }
    __syncthreads();

    // LN per row
    {
        float s = 0.f, sq = 0.f;
        for (int k = 0; k < 8; k++) {
            float v = hn[w][lane + 32 * k];
            s += v; sq += v * v;
        }
        #pragma unroll
        for (int o = 16; o > 0; o >>= 1) {
            s  += __shfl_xor_sync(0xffffffffu, s, o);
            sq += __shfl_xor_sync(0xffffffffu, sq, o);
        }
        float m = s * (1.f / DN);
        float var = sq * (1.f / DN) - m * m;
        float rs = rsqrtf(var + 1e-5f);
        for (int k = 0; k < 8; k++) {
            int c = lane + 32 * k;
            hn[w][c] = (hn[w][c] - m) * rs * g_ff[c] + b_ff[c];
        }
    }
    __syncthreads();

    // W1 (256x512) + relu
    for (int o = t; o < 2 * DN; o += 256) {
        float acc[8];
        #pragma unroll
        for (int r = 0; r < 8; r++) acc[r] = 0.f;
        for (int c = 0; c < DN; c++) {
            float wv = W1[c * 2 * DN + o];
            #pragma unroll
            for (int r = 0; r < 8; r++) acc[r] = fmaf(hn[r][c], wv, acc[r]);
        }
        float bb = b1[o];
        #pragma unroll
        for (int r = 0; r < 8; r++) h1[r][o] = fmaxf(acc[r] + bb, 0.f);
    }
    __syncthreads();

    // W2 (512x256) + bias + residual
    {
        float acc[8];
        #pragma unroll
        for (int r = 0; r < 8; r++) acc[r] = 0.f;
        for (int c = 0; c < 2 * DN; c++) {
            float wv = W2[c * DN + t];
            #pragma unroll
            for (int r = 0; r < 8; r++) acc[r] = fmaf(h1[r][c], wv, acc[r]);
        }
        float bb = b2[t];
        #pragma unroll
        for (int r = 0; r < 8; r++)
            out[(i0 + r) * DN + t] = node[(i0 + r) * DN + t] + acc[r] + bb;
    }
}

// ---------------- launch ----------------------------------------------------
extern "C" void kernel_launch(void* const* d_in, const int* in_sizes, int n_in,
                              void* d_out, int out_size) {
    const float* node     = (const float*)d_in[0];
    const float* edge     = (const float*)d_in[1];
    const float* bias     = (const float*)d_in[2];
    const float* node_pos = (const float*)d_in[3];
    const float* mask     = (const float*)d_in[4];
    const float* g_node   = (const float*)d_in[5];
    const float* b_node   = (const float*)d_in[6];
    const float* g_edge   = (const float*)d_in[7];
    const float* b_edge   = (const float*)d_in[8];
    const float* W_bias   = (const float*)d_in[9];
    const float* Wq       = (const float*)d_in[10];
    const float* Wk       = (const float*)d_in[11];
    const float* Wv       = (const float*)d_in[12];
    const float* Wb       = (const float*)d_in[13];
    const float* Wg       = (const float*)d_in[14];
    const float* bg       = (const float*)d_in[15];
    const float* Wo       = (const float*)d_in[16];
    const float* g_ff     = (const float*)d_in[17];
    const float* b_ff     = (const float*)d_in[18];
    const float* W1       = (const float*)d_in[19];
    const float* b1       = (const float*)d_in[20];
    const float* W2       = (const float*)d_in[21];
    const float* b2       = (const float*)d_in[22];
    float* out = (float*)d_out;

    cudaFuncSetAttribute(k3_attn, cudaFuncAttributeMaxDynamicSharedMemorySize,
                         TI * SPITCH * (int)sizeof(float));

    k0_precompute<<<1, 256>>>(g_edge, b_edge, W_bias, Wb);
    k1_node<<<128, 256>>>(node, node_pos, g_node, b_node, Wq, Wk, Wv, Wg, bg);
    k2_bterm<<<dim3(32, 1024), 256>>>(edge, bias);
    k3_attn<<<dim3(8, 64), 256, TI * SPITCH * sizeof(float)>>>(mask);
    k4_ffn<<<128, 256>>>(node, Wo, g_ff, b_ff, W1, b1, W2, b2, out);
}

// round 2
// speedup vs baseline: 1.4575x; 1.4575x over previous
#include <cuda_runtime.h>
#include <math.h>

#define N 1024
#define DN 256
#define DE 128
#define DB 64
#define DH 48
#define NH 8
#define DQ 384   // NH*DH

// ---------------- scratch (global device arrays; no runtime alloc) ----------
__device__ float d_GW[DE * NH];        // g_edge[c] * Wb[c][h]
__device__ float d_WF[DB * NH];        // (W_bias @ Wb)[d][h]
__device__ float d_SGW[NH];            // sum_c GW[c][h]
__device__ float d_BW[NH];             // b_edge . Wb[:,h]
__device__ float d_q[N * DQ];          // rope'd, pre-scaled by 1/16
__device__ float d_kT[DQ * N];         // [h*48+d][j]
__device__ float d_v[N * DQ];          // row major [j][h*48+d]
__device__ float d_gate[N * DQ];
__device__ float d_bt[(size_t)N * NH * N];  // [i][h][j]  (32 MB)
__device__ float d_ao[N * DQ];         // gated attention output

// ---------------- K0: tiny precompute -------------------------------------
__global__ void k0_precompute(const float* __restrict__ g_edge,
                              const float* __restrict__ b_edge,
                              const float* __restrict__ W_bias,
                              const float* __restrict__ Wb) {
    int t = threadIdx.x;
    for (int idx = t; idx < DE * NH; idx += 256) {
        int c = idx >> 3;
        d_GW[idx] = g_edge[c] * Wb[idx];
    }
    for (int idx = t; idx < DB * NH; idx += 256) {
        int dd = idx >> 3, h = idx & 7;
        float s = 0.f;
        for (int c = 0; c < DE; c++) s += W_bias[dd * DE + c] * Wb[c * NH + h];
        d_WF[idx] = s;
    }
    if (t < NH) {
        float s = 0.f, b = 0.f;
        for (int c = 0; c < DE; c++) {
            s += g_edge[c] * Wb[c * NH + t];
            b += b_edge[c] * Wb[c * NH + t];
        }
        d_SGW[t] = s;
        d_BW[t] = b;
    }
}

// ---------------- K1: node LN + QKVG + rope + gate -------------------------
__global__ void __launch_bounds__(256) k1_node(
        const float* __restrict__ node, const float* __restrict__ node_pos,
        const float* __restrict__ g_node, const float* __restrict__ b_node,
        const float* __restrict__ Wq, const float* __restrict__ Wk,
        const float* __restrict__ Wv, const float* __restrict__ Wg,
        const float* __restrict__ bg) {
    __shared__ float x[8][DN];
    __shared__ float qt[8][DQ];
    __shared__ float kt[8][DQ];
    int t = threadIdx.x;
    int i0 = blockIdx.x * 8;
    int w = t >> 5, lane = t & 31;

    for (int r = 0; r < 8; r++) x[r][t] = node[(i0 + r) * DN + t];
    __syncthreads();

    // LN: warp w handles row w
    {
        float s = 0.f, sq = 0.f;
        for (int k = 0; k < 8; k++) {
            float v = x[w][lane + 32 * k];
            s += v; sq += v * v;
        }
        for (int o = 16; o > 0; o >>= 1) {
            s  += __shfl_xor_sync(0xffffffffu, s, o);
            sq += __shfl_xor_sync(0xffffffffu, sq, o);
        }
        float m = s * (1.f / DN);
        float var = sq * (1.f / DN) - m * m;
        float rs = rsqrtf(var + 1e-5f);
        for (int k = 0; k < 8; k++) {
            int c = lane + 32 * k;
            x[w][c] = (x[w][c] - m) * rs * g_node[c] + b_node[c];
        }
    }
    __syncthreads();

    // q, k raw
    for (int o = t; o < DQ; o += 256) {
        float acc[8];
        #pragma unroll
        for (int r = 0; r < 8; r++) acc[r] = 0.f;
        for (int c = 0; c < DN; c++) {
            float wv = Wq[c * DQ + o];
            #pragma unroll
            for (int r = 0; r < 8; r++) acc[r] = fmaf(x[r][c], wv, acc[r]);
        }
        #pragma unroll
        for (int r = 0; r < 8; r++) qt[r][o] = acc[r];

        #pragma unroll
        for (int r = 0; r < 8; r++) acc[r] = 0.f;
        for (int c = 0; c < DN; c++) {
            float wv = Wk[c * DQ + o];
            #pragma unroll
            for (int r = 0; r < 8; r++) acc[r] = fmaf(x[r][c], wv, acc[r]);
        }
        #pragma unroll
        for (int r = 0; r < 8; r++) kt[r][o] = acc[r];
    }
    __syncthreads();

    // rope + store q (scaled), kT
    for (int idx = t; idx < 8 * DQ; idx += 256) {
        int r = idx / DQ, o = idx % DQ;
        int h = o / DH, d = o % DH;
        int dd = (d < 24) ? d : d - 24;
        float pos = node_pos[i0 + r];
        float invf = expf(-0.38376418216567434f * (float)dd);  // ln(1e4)/24
        float th = pos * invf;
        float cs, sn;
        sincosf(th, &sn, &cs);
        float q1 = qt[r][h * DH + dd], q2 = qt[r][h * DH + dd + 24];
        float k1 = kt[r][h * DH + dd], k2 = kt[r][h * DH + dd + 24];
        float qv = (d < 24) ? (q1 * cs - q2 * sn) : (q1 * sn + q2 * cs);
        float kv = (d < 24) ? (k1 * cs - k2 * sn) : (k1 * sn + k2 * cs);
        d_q[(i0 + r) * DQ + o] = qv * 0.0625f;  // 1/sqrt(256)
        d_kT[o * N + (i0 + r)] = kv;
    }

    // v, gate
    for (int o = t; o < DQ; o += 256) {
        float acc[8];
        #pragma unroll
        for (int r = 0; r < 8; r++) acc[r] = 0.f;
        for (int c = 0; c < DN; c++) {
            float wv = Wv[c * DQ + o];
            #pragma unroll
            for (int r = 0; r < 8; r++) acc[r] = fmaf(x[r][c], wv, acc[r]);
        }
        #pragma unroll
        for (int r = 0; r < 8; r++) d_v[(i0 + r) * DQ + o] = acc[r];

        #pragma unroll
        for (int r = 0; r < 8; r++) acc[r] = 0.f;
        for (int c = 0; c < DN; c++) {
            float wv = Wg[c * DQ + o];
            #pragma unroll
            for (int r = 0; r < 8; r++) acc[r] = fmaf(x[r][c], wv, acc[r]);
        }
        #pragma unroll
        for (int r = 0; r < 8; r++) {
            float z = acc[r] + bg[o];
            d_gate[(i0 + r) * DQ + o] = 1.f / (1.f + __expf(-z));
        }
    }
}

// ---------------- K2 v2: b_term from edge+bias (HBM-bound) -----------------
// One block per row i. 8 warps, warp w handles j = step*8 + w, step 0..127.
// Coefficients loaded ONCE per block. Depth-2 prefetch. Folded reductions.
__global__ void __launch_bounds__(256) k2_bterm(const float* __restrict__ edge,
                                                const float* __restrict__ bias) {
    __shared__ float sb[NH][32];
    int t = threadIdx.x;
    int w = t >> 5, lane = t & 31;
    int i = blockIdx.x;

    // register-resident coefficients (lane-dependent), loaded once
    float GWr[4][8], WFr[2][8];
    #pragma unroll
    for (int cc = 0; cc < 4; cc++) {
        const float* p = &d_GW[(lane * 4 + cc) * 8];
        float4 a = *(const float4*)p;
        float4 b = *(const float4*)(p + 4);
        GWr[cc][0] = a.x; GWr[cc][1] = a.y; GWr[cc][2] = a.z; GWr[cc][3] = a.w;
        GWr[cc][4] = b.x; GWr[cc][5] = b.y; GWr[cc][6] = b.z; GWr[cc][7] = b.w;
    }
    #pragma unroll
    for (int cc = 0; cc < 2; cc++) {
        const float* p = &d_WF[(lane * 2 + cc) * 8];
        float4 a = *(const float4*)p;
        float4 b = *(const float4*)(p + 4);
        WFr[cc][0] = a.x; WFr[cc][1] = a.y; WFr[cc][2] = a.z; WFr[cc][3] = a.w;
        WFr[cc][4] = b.x; WFr[cc][5] = b.y; WFr[cc][6] = b.z; WFr[cc][7] = b.w;
    }
    float SGWl = d_SGW[lane & 7];
    float BWl  = d_BW[lane & 7];

    const float* ebase = edge + (size_t)i * N * DE + lane * 4;
    const float* bbase = bias + (size_t)i * N * DB + lane * 2;

    // depth-2 prefetch pipeline over j = step*8 + w
    float4 eA = *(const float4*)(ebase + (size_t)(0 * 8 + w) * DE);
    float2 bA = *(const float2*)(bbase + (size_t)(0 * 8 + w) * DB);
    float4 eB = *(const float4*)(ebase + (size_t)(1 * 8 + w) * DE);
    float2 bB = *(const float2*)(bbase + (size_t)(1 * 8 + w) * DB);

    for (int step = 0; step < 128; step++) {
        float4 e = eA; float2 bv = bA;
        eA = eB; bA = bB;
        if (step < 126) {
            int jn = (step + 2) * 8 + w;
            eB = *(const float4*)(ebase + (size_t)jn * DE);
            bB = *(const float2*)(bbase + (size_t)jn * DB);
        }

        // sum / sumsq fold: even lanes carry s, odd carry sq, then butterflies
        float s  = e.x + e.y + e.z + e.w;
        float sq = e.x * e.x + e.y * e.y + e.z * e.z + e.w * e.w;
        bool odd = (lane & 1);
        float t1 = odd ? s : sq;
        t1 = __shfl_xor_sync(0xffffffffu, t1, 1);
        float u = (odd ? sq : s) + t1;
        u += __shfl_xor_sync(0xffffffffu, u, 2);
        u += __shfl_xor_sync(0xffffffffu, u, 4);
        u += __shfl_xor_sync(0xffffffffu, u, 8);
        u += __shfl_xor_sync(0xffffffffu, u, 16);
        float other = __shfl_xor_sync(0xffffffffu, u, 1);
        float sf  = odd ? other : u;
        float sqf = odd ? u : other;
        float m = sf * (1.f / DE);
        float var = sqf * (1.f / DE) - m * m;
        float rs = rsqrtf(var + 1e-5f);

        // per-lane partial for all 8 heads
        float comb[8];
        #pragma unroll
        for (int h = 0; h < 8; h++) {
            float te = e.x * GWr[0][h] + e.y * GWr[1][h] + e.z * GWr[2][h] + e.w * GWr[3][h];
            float tb = bv.x * WFr[0][h] + bv.y * WFr[1][h];
            comb[h] = fmaf(rs, te, tb);
        }
        // fold: 8 values -> lane l (l<8) holds full sum of comb[l]
        float c4[4];
        #pragma unroll
        for (int k = 0; k < 4; k++) {
            bool hi = (lane & 1);
            float a = comb[2 * k], b = comb[2 * k + 1];
            float tt = hi ? a : b;
            tt = __shfl_xor_sync(0xffffffffu, tt, 1);
            c4[k] = (hi ? b : a) + tt;
        }
        float c2[2];
        #pragma unroll
        for (int k = 0; k < 2; k++) {
            bool hi = (lane & 2);
            float a = c4[2 * k], b = c4[2 * k + 1];
            float tt = hi ? a : b;
            tt = __shfl_xor_sync(0xffffffffu, tt, 2);
            c2[k] = (hi ? b : a) + tt;
        }
        float c1;
        {
            bool hi = (lane & 4);
            float a = c2[0], b = c2[1];
            float tt = hi ? a : b;
            tt = __shfl_xor_sync(0xffffffffu, tt, 4);
            c1 = (hi ? b : a) + tt;
        }
        c1 += __shfl_xor_sync(0xffffffffu, c1, 8);
        c1 += __shfl_xor_sync(0xffffffffu, c1, 16);

        if (lane < 8) {
            int jj = ((step & 3) << 3) + w;
            sb[lane][jj] = c1 - rs * m * SGWl + BWl;
        }

        if ((step & 3) == 3) {
            __syncthreads();
            int h = t >> 5, jj = t & 31;
            int chunk = step >> 2;
            d_bt[((size_t)i * NH + h) * N + chunk * 32 + jj] = sb[h][jj];
            __syncthreads();
        }
    }
}

// ---------------- K3 v2: attention (per head, 16-row i tile) ----------------
#define TI 16
#define SPITCH 1025
__global__ void __launch_bounds__(256, 3) k3_attn(const float* __restrict__ mask) {
    extern __shared__ float ss[];            // [TI][SPITCH]
    __shared__ float qs[TI * DH];
    __shared__ float inv[TI];
    __shared__ float maskr[TI];
    int t = threadIdx.x;
    int h = blockIdx.x;
    int i0 = blockIdx.y * TI;
    int w = t >> 5, lane = t & 31;

    for (int idx = t; idx < TI * DH; idx += 256) {
        int r = idx / DH, d = idx % DH;
        qs[idx] = d_q[(i0 + r) * DQ + h * DH + d];
    }
    if (t < TI) maskr[t] = mask[i0 + t];
    __syncthreads();

    // scores: batch DRAM bt loads first (MLP=16), overlap with L2 kT d-loop
    for (int jj = 0; jj < 4; jj++) {
        int j = t + jj * 256;
        float btv[TI];
        #pragma unroll
        for (int r = 0; r < TI; r++)
            btv[r] = d_bt[((size_t)(i0 + r) * NH + h) * N + j];
        float acc[TI];
        #pragma unroll
        for (int r = 0; r < TI; r++) acc[r] = 0.f;
        #pragma unroll 4
        for (int d = 0; d < DH; d++) {
            float kv = d_kT[(h * DH + d) * N + j];
            #pragma unroll
            for (int r = 0; r < TI; r++) acc[r] = fmaf(qs[r * DH + d], kv, acc[r]);
        }
        float mj = mask[j];
        #pragma unroll
        for (int r = 0; r < TI; r++) {
            float sm = 1000000.0f * (maskr[r] * mj - 1.f);
            ss[r * SPITCH + j] = acc[r] + btv[r] + sm;
        }
    }
    __syncthreads();

    // softmax over j (warp per 2 rows); keep unnormalized e, save 1/sum
    for (int rr = 0; rr < 2; rr++) {
        int r = w * 2 + rr;
        float mx = -1e30f;
        for (int k = 0; k < 32; k++)
            mx = fmaxf(mx, ss[r * SPITCH + lane + 32 * k]);
        #pragma unroll
        for (int o = 16; o > 0; o >>= 1)
            mx = fmaxf(mx, __shfl_xor_sync(0xffffffffu, mx, o));
        float sum = 0.f;
        for (int k = 0; k < 32; k++) {
            int c = r * SPITCH + lane + 32 * k;
            float ev = __expf(ss[c] - mx);
            ss[c] = ev;
            sum += ev;
        }
        #pragma unroll
        for (int o = 16; o > 0; o >>= 1)
            sum += __shfl_xor_sync(0xffffffffu, sum, o);
        if (lane == 0) inv[r] = 1.f / sum;
    }
    __syncthreads();

    // PV: all 256 threads. t -> (quarter q4, row rr, dim-third d3)
    int q4 = t >> 6;          // 0..3  (j in [q4*256, q4*256+256))
    int rr = (t & 63) >> 2;   // 0..15
    int d3 = t & 3;           // 0..3  -> dims [d3*12, d3*12+12)
    float4 a0 = make_float4(0.f, 0.f, 0.f, 0.f);
    float4 a1 = a0, a2 = a0;
    {
        const float* vb = d_v + h * DH + d3 * 12;
        const float* pr = &ss[rr * SPITCH + q4 * 256];
        const float* vp = vb + (size_t)(q4 * 256) * DQ;
        #pragma unroll 4
        for (int j = 0; j < 256; j++) {
            float p = pr[j];
            float4 v0 = *(const float4*)(vp);
            float4 v1 = *(const float4*)(vp + 4);
            float4 v2 = *(const float4*)(vp + 8);
            a0.x = fmaf(p, v0.x, a0.x); a0.y = fmaf(p, v0.y, a0.y);
            a0.z = fmaf(p, v0.z, a0.z); a0.w = fmaf(p, v0.w, a0.w);
            a1.x = fmaf(p, v1.x, a1.x); a1.y = fmaf(p, v1.y, a1.y);
            a1.z = fmaf(p, v1.z, a1.z); a1.w = fmaf(p, v1.w, a1.w);
            a2.x = fmaf(p, v2.x, a2.x); a2.y = fmaf(p, v2.y, a2.y);
            a2.z = fmaf(p, v2.z, a2.z); a2.w = fmaf(p, v2.w, a2.w);
            vp += DQ;
        }
    }
    __syncthreads();   // all reads of ss done
    // store partials into ss scratch: base = ((q4*16+rr)*4+d3)*12 floats
    {
        float* pp = &ss[(((q4 * 16 + rr) * 4 + d3) * 12)];
        *(float4*)(pp + 0) = a0;
        *(float4*)(pp + 4) = a1;
        *(float4*)(pp + 8) = a2;
    }
    __syncthreads();
    if (t < TI * 12) {
        int r = t / 12, dq = t % 12;
        int d3r = dq / 3, off = (dq % 3) * 4;
        float4 s = make_float4(0.f, 0.f, 0.f, 0.f);
        #pragma unroll
        for (int q = 0; q < 4; q++) {
            float4 p = *(const float4*)&ss[(((q * 16 + r) * 4 + d3r) * 12) + off];
            s.x += p.x; s.y += p.y; s.z += p.z; s.w += p.w;
        }
        float iv = inv[r];
        int gi = (i0 + r) * DQ + h * DH + dq * 4;
        float4 g4 = *(const float4*)&d_gate[gi];
        float4 o4;
        o4.x = s.x * iv * g4.x;
        o4.y = s.y * iv * g4.y;
        o4.z = s.z * iv * g4.z;
        o4.w = s.w * iv * g4.w;
        *(float4*)&d_ao[gi] = o4;
    }
}

// ---------------- K4: Wo + LN + FFN + residual ------------------------------
__global__ void __launch_bounds__(256) k4_ffn(
        const float* __restrict__ node,
        const float* __restrict__ Wo, const float* __restrict__ g_ff,
        const float* __restrict__ b_ff, const float* __restrict__ W1,
        const float* __restrict__ b1, const float* __restrict__ W2,
        const float* __restrict__ b2, float* __restrict__ out) {
    __shared__ float ao[8][DQ];
    __shared__ float hn[8][DN];
    __shared__ float h1[8][2 * DN];
    int t = threadIdx.x;
    int i0 = blockIdx.x * 8;
    int w = t >> 5, lane = t & 31;

    for (int idx = t; idx < 8 * DQ; idx += 256) {
        int r = idx / DQ, c = idx % DQ;
        ao[r][c] = d_ao[(i0 + r) * DQ + c];
    }
    __syncthreads();

    // out-projection (Wo: 384x256)
    {
        float acc[8];
        #pragma unroll
        for (int r = 0; r < 8; r++) acc[r] = 0.f;
        for (int c = 0; c < DQ; c++) {
            float wv = Wo[c * DN + t];
            #pragma unroll
            for (int r = 0; r < 8; r++) acc[r] = fmaf(ao[r][c], wv, acc[r]);
        }
        #pragma unroll
        for (int r = 0; r < 8; r++) hn[r][t] = acc[r];
    }
    __syncthreads();

    // LN per row
    {
        float s = 0.f, sq = 0.f;
        for (int k = 0; k < 8; k++) {
            float v = hn[w][lane + 32 * k];
            s += v; sq += v * v;
        }
        #pragma unroll
        for (int o = 16; o > 0; o >>= 1) {
            s  += __shfl_xor_sync(0xffffffffu, s, o);
            sq += __shfl_xor_sync(0xffffffffu, sq, o);
        }
        float m = s * (1.f / DN);
        float var = sq * (1.f / DN) - m * m;
        float rs = rsqrtf(var + 1e-5f);
        for (int k = 0; k < 8; k++) {
            int c = lane + 32 * k;
            hn[w][c] = (hn[w][c] - m) * rs * g_ff[c] + b_ff[c];
        }
    }
    __syncthreads();

    // W1 (256x512) + relu
    for (int o = t; o < 2 * DN; o += 256) {
        float acc[8];
        #pragma unroll
        for (int r = 0; r < 8; r++) acc[r] = 0.f;
        for (int c = 0; c < DN; c++) {
            float wv = W1[c * 2 * DN + o];
            #pragma unroll
            for (int r = 0; r < 8; r++) acc[r] = fmaf(hn[r][c], wv, acc[r]);
        }
        float bb = b1[o];
        #pragma unroll
        for (int r = 0; r < 8; r++) h1[r][o] = fmaxf(acc[r] + bb, 0.f);
    }
    __syncthreads();

    // W2 (512x256) + bias + residual
    {
        float acc[8];
        #pragma unroll
        for (int r = 0; r < 8; r++) acc[r] = 0.f;
        for (int c = 0; c < 2 * DN; c++) {
            float wv = W2[c * DN + t];
            #pragma unroll
            for (int r = 0; r < 8; r++) acc[r] = fmaf(h1[r][c], wv, acc[r]);
        }
        float bb = b2[t];
        #pragma unroll
        for (int r = 0; r < 8; r++)
            out[(i0 + r) * DN + t] = node[(i0 + r) * DN + t] + acc[r] + bb;
    }
}

// ---------------- launch ----------------------------------------------------
extern "C" void kernel_launch(void* const* d_in, const int* in_sizes, int n_in,
                              void* d_out, int out_size) {
    const float* node     = (const float*)d_in[0];
    const float* edge     = (const float*)d_in[1];
    const float* bias     = (const float*)d_in[2];
    const float* node_pos = (const float*)d_in[3];
    const float* mask     = (const float*)d_in[4];
    const float* g_node   = (const float*)d_in[5];
    const float* b_node   = (const float*)d_in[6];
    const float* g_edge   = (const float*)d_in[7];
    const float* b_edge   = (const float*)d_in[8];
    const float* W_bias   = (const float*)d_in[9];
    const float* Wq       = (const float*)d_in[10];
    const float* Wk       = (const float*)d_in[11];
    const float* Wv       = (const float*)d_in[12];
    const float* Wb       = (const float*)d_in[13];
    const float* Wg       = (const float*)d_in[14];
    const float* bg       = (const float*)d_in[15];
    const float* Wo       = (const float*)d_in[16];
    const float* g_ff     = (const float*)d_in[17];
    const float* b_ff     = (const float*)d_in[18];
    const float* W1       = (const float*)d_in[19];
    const float* b1       = (const float*)d_in[20];
    const float* W2       = (const float*)d_in[21];
    const float* b2       = (const float*)d_in[22];
    float* out = (float*)d_out;

    cudaFuncSetAttribute(k3_attn, cudaFuncAttributeMaxDynamicSharedMemorySize,
                         TI * SPITCH * (int)sizeof(float));

    k0_precompute<<<1, 256>>>(g_edge, b_edge, W_bias, Wb);
    k1_node<<<128, 256>>>(node, node_pos, g_node, b_node, Wq, Wk, Wv, Wg, bg);
    k2_bterm<<<1024, 256>>>(edge, bias);
    k3_attn<<<dim3(8, 64), 256, TI * SPITCH * sizeof(float)>>>(mask);
    k4_ffn<<<128, 256>>>(node, Wo, g_ff, b_ff, W1, b1, W2, b2, out);
}